// round 16
// baseline (speedup 1.0000x reference)
#include <cuda_runtime.h>
#include <cuda_fp16.h>
#include <cstdint>

#define NUM_V 100000
#define NUM_R 1000
#define DV 192   // D+I (K dim of V projection)
#define DR 128
#define H 128
#define B 4096
#define N 64
#define ARITY 3

#define VT_ROWS 32                     // V rows per tile
#define NTILES  (NUM_V / VT_ROWS)      // 3125 (exact)
#define NJ      6                      // j = k32 chunk (2 MMAs each)
#define KK      96                     // half2 per row
#define GRID    296                    // 2 CTAs/SM x 148 SMs

// smem word map: A double buffer [0, 6400) (row stride 100 words, 32 rows/buf),
// stage [6400, 8576)
#define AROW_W     100                 // A row stride in 4B words (100%32==4)
#define ABUF_W     3200                // one A buffer in words
#define STAGE_W    6400
#define STAGE_ROWW 68                  // stage row stride in words (68%32==4)
#define SMEM_BYTES ((STAGE_W + VT_ROWS * STAGE_ROWW) * 4)   // 34304

__device__ __align__(16) __half g_VW[NUM_V * H];  // 25.6 MB fp16
__device__ __align__(16) __half g_XR[NUM_R * H];  // fp16
__device__ __align__(16) float  g_pp[H];

// ---------------------------------------------------------------------------
// helpers
// ---------------------------------------------------------------------------
__device__ __forceinline__ unsigned pack_h2(float lo, float hi) {
    unsigned r;
    asm("cvt.rn.f16x2.f32 %0, %1, %2;" : "=r"(r) : "f"(hi), "f"(lo));
    return r;
}

__device__ __forceinline__ uint32_t smem_u32(const void* p) {
    uint32_t a;
    asm("{ .reg .u64 t; cvta.to.shared.u64 t, %1; cvt.u32.u64 %0, t; }" : "=r"(a) : "l"(p));
    return a;
}

__device__ __forceinline__ void ldmatrix_x4(unsigned a[4], uint32_t addr) {
    asm volatile("ldmatrix.sync.aligned.m8n8.x4.shared.b16 {%0,%1,%2,%3}, [%4];"
                 : "=r"(a[0]), "=r"(a[1]), "=r"(a[2]), "=r"(a[3]) : "r"(addr));
}

__device__ __forceinline__ void mma16816f16(float c[4], const unsigned a[4],
                                            unsigned b0, unsigned b1) {
    asm volatile(
        "mma.sync.aligned.m16n8k16.row.col.f32.f16.f16.f32 "
        "{%0,%1,%2,%3},{%4,%5,%6,%7},{%8,%9},{%0,%1,%2,%3};\n"
        : "+f"(c[0]), "+f"(c[1]), "+f"(c[2]), "+f"(c[3])
        : "r"(a[0]), "r"(a[1]), "r"(a[2]), "r"(a[3]), "r"(b0), "r"(b1));
}

// ---------------------------------------------------------------------------
// Kernel: prep (fused) + VW = V@WV + bV via fp16 mma.sync.
// 296 blocks (2 CTAs/SM) x 256 threads. Natural row-major A layout in smem.
// Pipeline: top = 6 STS.64 of pre-packed pv16; LDG next tile mid-iteration;
// convert f32->fp16 at bottom (LDG has epi1+sync+epi2 of slack).
// Only uint2 pv16[6] (12 regs) lives across the iteration boundary.
// ---------------------------------------------------------------------------
__global__ void __launch_bounds__(256, 2)
vproj_kernel(const float* __restrict__ V, const float* __restrict__ WV,
             const float* __restrict__ bV,
             const float* __restrict__ R, const float* __restrict__ WR,
             const float* __restrict__ bR,
             const float* __restrict__ P, const float* __restrict__ WP,
             const float* __restrict__ bP) {
    extern __shared__ unsigned smw[];
    __shared__ float sR[8 * DR];

    int tid = threadIdx.x;
    int w = tid >> 5, lane = tid & 31;
    int g = lane >> 2, tg = lane & 3;
    int nb = w * 16;
    int blk = blockIdx.x;

    // ---------------- fused prep: XR (blocks 0..124), pp (block 125) --------
    if (blk < 125) {
        int h = tid & 127;
        if (tid < 128) {
            #pragma unroll
            for (int k = 0; k < 8; k++) sR[k * DR + h] = R[(size_t)(8 * blk + k) * DR + h];
        }
        __syncthreads();
        if (tid < 128) {
            float acc[8];
            float bias = bR[h];
            #pragma unroll
            for (int k = 0; k < 8; k++) acc[k] = bias;
            #pragma unroll 4
            for (int d = 0; d < DR; d++) {
                float wv = WR[d * H + h];
                #pragma unroll
                for (int k = 0; k < 8; k++) acc[k] = fmaf(sR[k * DR + d], wv, acc[k]);
            }
            #pragma unroll
            for (int k = 0; k < 8; k++)
                g_XR[(size_t)(8 * blk + k) * H + h] = __float2half_rn(acc[k]);
        }
        __syncthreads();
    } else if (blk == 125) {
        int h = tid & 127;
        if (tid < 128) {
            for (int i = h; i < ARITY * DR; i += 128) sR[i] = P[i];
        }
        __syncthreads();
        if (tid < 128) {
            float prod = 1.0f;
            for (int a = 0; a < ARITY; a++) {
                float acc = bP[h];
                #pragma unroll 4
                for (int d = 0; d < DR; d++) acc = fmaf(sR[a * DR + d], WP[d * H + h], acc);
                prod *= acc;
            }
            g_pp[h] = prod;
        }
        __syncthreads();
    }

    // ---------------- stage W in two halves; read fragments to registers ----
    unsigned Bf[NJ][2][2][2];   // [j][ks][nt][b0/b1]
    {
        int half = nb >> 6;
        int nloc = nb & 63;
        for (int rep = 0; rep < 2; rep++) {
            __syncthreads();
            for (int idx = tid; idx < 64 * KK; idx += 256) {
                int n = idx & 63, kk = idx >> 6;
                int gn = 64 * rep + n;
                smw[n * AROW_W + kk] = pack_h2(WV[(2 * kk) * H + gn],
                                               WV[(2 * kk + 1) * H + gn]);
            }
            __syncthreads();
            if (half == rep) {
                #pragma unroll
                for (int j = 0; j < NJ; j++)
                    #pragma unroll
                    for (int ks = 0; ks < 2; ks++)
                        #pragma unroll
                        for (int nt = 0; nt < 2; nt++) {
                            int nc = nloc + nt * 8 + g;
                            int kb = 16 * j + 8 * ks + tg;
                            Bf[j][ks][nt][0] = smw[nc * AROW_W + kb];
                            Bf[j][ks][nt][1] = smw[nc * AROW_W + kb + 4];
                        }
            }
        }
    }
    float bvx[2], bvy[2];
    #pragma unroll
    for (int nt = 0; nt < 2; nt++) {
        int col = nb + nt * 8 + 2 * tg;
        bvx[nt] = bV[col];
        bvy[nt] = bV[col + 1];
    }
    __syncthreads();   // smem becomes A double buffer + stage

    uint32_t smb = smem_u32(smw);
    uint32_t lmbase = smb + (uint32_t)((lane & 15) * (AROW_W * 4)) + (uint32_t)((lane >> 4) * 16);

    int crow = tid >> 3, cpart = tid & 7;
    int sbase = crow * AROW_W + 2 * cpart;

    // ---------------- prologue: LDG + convert tile blk into pv16 ------------
    uint2 pv16[NJ];
    int t = blk;
    if (t < NTILES) {
        const float4* src = (const float4*)(V + (size_t)(t * VT_ROWS + crow) * DV) + cpart;
        #pragma unroll
        for (int j = 0; j < NJ; j++) {
            float4 v = src[8 * j];
            pv16[j].x = pack_h2(v.x, v.y);
            pv16[j].y = pack_h2(v.z, v.w);
        }
    }

    int bufW = 0;
    for (; t < NTILES; t += GRID) {
        int tn = t + GRID;

        // --- top: store pre-packed tile t into write buffer (6 STS.64) ---
        {
            unsigned* dst = smw + bufW * ABUF_W + sbase;
            #pragma unroll
            for (int j = 0; j < NJ; j++) *(uint2*)(dst + 16 * j) = pv16[j];
        }

        // --- LDG next tile (consumed by cvt at the bottom: epi1+sync+epi2 slack)
        float4 pv[NJ];
        if (tn < NTILES) {
            const float4* src = (const float4*)(V + (size_t)(tn * VT_ROWS + crow) * DV) + cpart;
            #pragma unroll
            for (int j = 0; j < NJ; j++) pv[j] = src[8 * j];
        }
        __syncthreads();   // bufW tile ready; prev copy-out done

        // --- MMA on bufW: ldmatrix A, B from registers ---
        uint32_t abase = lmbase + (uint32_t)(bufW * (ABUF_W * 4));
        float c[2][2][4];
        #pragma unroll
        for (int rg = 0; rg < 2; rg++)
            #pragma unroll
            for (int nt = 0; nt < 2; nt++)
                #pragma unroll
                for (int i = 0; i < 4; i++) c[rg][nt][i] = 0.f;

        #pragma unroll
        for (int j = 0; j < NJ; j++) {
            unsigned af[2][2][4];   // [rg][ks][4]
            #pragma unroll
            for (int rg = 0; rg < 2; rg++)
                #pragma unroll
                for (int ks = 0; ks < 2; ks++)
                    ldmatrix_x4(af[rg][ks],
                                abase + (uint32_t)(rg * 16 * AROW_W * 4 + j * 64 + ks * 32));
            #pragma unroll
            for (int rg = 0; rg < 2; rg++)
                #pragma unroll
                for (int nt = 0; nt < 2; nt++) {
                    mma16816f16(c[rg][nt], af[rg][0], Bf[j][0][nt][0], Bf[j][0][nt][1]);
                    mma16816f16(c[rg][nt], af[rg][1], Bf[j][1][nt][0], Bf[j][1][nt][1]);
                }
        }

        // --- epilogue part 1: accumulators (+bias, fp16) -> padded stage ----
        {
            unsigned* stg = smw + STAGE_W;
            #pragma unroll
            for (int rg = 0; rg < 2; rg++) {
                int r0 = rg * 16 + g;
                #pragma unroll
                for (int nt = 0; nt < 2; nt++) {
                    int cw = (nb >> 1) + nt * 4 + tg;
                    unsigned p0 = pack_h2(c[rg][nt][0] + bvx[nt], c[rg][nt][1] + bvy[nt]);
                    unsigned p1 = pack_h2(c[rg][nt][2] + bvx[nt], c[rg][nt][3] + bvy[nt]);
                    stg[r0 * STAGE_ROWW + cw] = p0;
                    stg[(r0 + 8) * STAGE_ROWW + cw] = p1;
                }
            }
        }
        __syncthreads();   // stage complete; bufW ldmatrix reads done

        // --- epilogue part 2: coalesced copy-out (stage -> g_VW) ------------
        {
            const uint4* stg4 = (const uint4*)(smw + STAGE_W);
            uint4* out4 = (uint4*)g_VW;
            #pragma unroll
            for (int k = 0; k < 2; k++) {
                int idx = tid + k * 256;        // 512 = 32 rows * 16 uint4
                int row = idx >> 4, q = idx & 15;
                int grow = t * VT_ROWS + row;
                out4[(size_t)grow * 16 + q] = stg4[row * 17 + q];
            }
        }

        // --- bottom: convert next tile to packed fp16 (LDG data has arrived)
        if (tn < NTILES) {
            #pragma unroll
            for (int j = 0; j < NJ; j++) {
                pv16[j].x = pack_h2(pv[j].x, pv[j].y);
                pv16[j].y = pack_h2(pv[j].z, pv[j].w);
            }
        }
        bufW ^= 1;
    }
}

// ---------------------------------------------------------------------------
// Kernel: out[b,h] = pp[h] * sum_n XR[r[b,n],h] * VW[e0]*VW[e1]*VW[e2]
// ---------------------------------------------------------------------------
__global__ void __launch_bounds__(128)
gather_kernel(const int* __restrict__ r, const int* __restrict__ e,
              float* __restrict__ out) {
    __shared__ int sidx[4 * N];
    __shared__ float4 sacc[128];
    int tid = threadIdx.x;
    int w = tid >> 5, l = tid & 31;
    int b = blockIdx.x;
    for (int i = tid; i < 4 * N; i += 128) {
        int k = i >> 6, n = i & 63;
        sidx[i] = (k == 0) ? r[b * N + n] : e[(k - 1) * (B * N) + b * N + n];
    }
    __syncthreads();

    const uint2* XR2 = (const uint2*)g_XR;
    const uint2* VW2 = (const uint2*)g_VW;
    float4 acc = make_float4(0.f, 0.f, 0.f, 0.f);
    #pragma unroll 4
    for (int i = 0; i < 16; i++) {
        int n = w + i * 4;
        int ir = sidx[n];
        int i0 = sidx[64 + n];
        int i1 = sidx[128 + n];
        int i2 = sidx[192 + n];
        uint2 ux = XR2[ir * 32 + l];
        uint2 u0 = VW2[i0 * 32 + l];
        uint2 u1 = VW2[i1 * 32 + l];
        uint2 u2 = VW2[i2 * 32 + l];
        float2 xa = __half22float2(*(const __half2*)&ux.x);
        float2 xb = __half22float2(*(const __half2*)&ux.y);
        float2 a0 = __half22float2(*(const __half2*)&u0.x);
        float2 b0 = __half22float2(*(const __half2*)&u0.y);
        float2 a1 = __half22float2(*(const __half2*)&u1.x);
        float2 b1 = __half22float2(*(const __half2*)&u1.y);
        float2 a2 = __half22float2(*(const __half2*)&u2.x);
        float2 b2 = __half22float2(*(const __half2*)&u2.y);
        acc.x += xa.x * (a0.x * (a1.x * a2.x));
        acc.y += xa.y * (a0.y * (a1.y * a2.y));
        acc.z += xb.x * (b0.x * (b1.x * b2.x));
        acc.w += xb.y * (b0.y * (b1.y * b2.y));
    }
    sacc[tid] = acc;
    __syncthreads();
    if (w == 0) {
        float4 a0 = sacc[l], a1 = sacc[32 + l], a2 = sacc[64 + l], a3 = sacc[96 + l];
        float4 pp = ((const float4*)g_pp)[l];
        float4 o;
        o.x = (a0.x + a1.x + a2.x + a3.x) * pp.x;
        o.y = (a0.y + a1.y + a2.y + a3.y) * pp.y;
        o.z = (a0.z + a1.z + a2.z + a3.z) * pp.z;
        o.w = (a0.w + a1.w + a2.w + a3.w) * pp.w;
        ((float4*)out)[b * 32 + l] = o;
    }
}

// ---------------------------------------------------------------------------
extern "C" void kernel_launch(void* const* d_in, const int* in_sizes, int n_in,
                              void* d_out, int out_size) {
    const int*   r  = (const int*)d_in[0];
    const int*   e  = (const int*)d_in[1];
    const float* V  = (const float*)d_in[2];
    const float* R  = (const float*)d_in[3];
    const float* P  = (const float*)d_in[4];
    const float* WV = (const float*)d_in[5];
    const float* bV = (const float*)d_in[6];
    const float* WR = (const float*)d_in[7];
    const float* bR = (const float*)d_in[8];
    const float* WP = (const float*)d_in[9];
    const float* bP = (const float*)d_in[10];
    float* out = (float*)d_out;

    cudaFuncSetAttribute(vproj_kernel, cudaFuncAttributeMaxDynamicSharedMemorySize, SMEM_BYTES);

    vproj_kernel<<<GRID, 256, SMEM_BYTES>>>(V, WV, bV, R, WR, bR, P, WP, bP);
    gather_kernel<<<B, 128>>>(r, e, out);
}